// round 5
// baseline (speedup 1.0000x reference)
#include <cuda_runtime.h>
#include <cstdint>

// ---------------------------------------------------------------------------
// SparseGaussianHead: two sparse-conv layers (27-offset gather-GEMM) + GELU
//   L1: [400k x 64] -> [400k x 38]   (N padded to 40)
//   L2: [400k x 38] -> [400k x 38]   (K and N padded to 40)
// TF32 mma.sync.m16n8k8, fp32 accumulate, cvt.rna.tf32 pre-rounding.
// R4: validity-skipping gather (~87% of neighbor slots are invalid/zero),
//     per-tile MMA skip via ballot, double-buffered W prefetch.
// ---------------------------------------------------------------------------

#define NPTS 400000
#define NOFF 27

__device__ float g_featp[NPTS * 64];      // features pre-rounded to tf32
__device__ float g_h[NPTS * 40];          // intermediate (gelu out), cols 38..39 = 0
__device__ float g_W1p[NOFF * 64 * 40];   // W1 padded + tf32-rounded
__device__ float g_W2p[NOFF * 40 * 40];   // W2 padded + tf32-rounded

__device__ __forceinline__ float tf32r(float x) {
    unsigned u;
    asm("cvt.rna.tf32.f32 %0, %1;" : "=r"(u) : "f"(x));
    return __uint_as_float(u);
}

__device__ __forceinline__ float gelu_exact(float x) {
    return 0.5f * x * (1.0f + erff(x * 0.7071067811865476f));
}

// ------------------------------ prep kernels ------------------------------

__global__ void prep_feat(const float* __restrict__ F) {
    int e = blockIdx.x * 256 + threadIdx.x;   // grid covers NPTS*64 exactly
    g_featp[e] = tf32r(F[e]);
}

__global__ void prep_w1(const float* __restrict__ W1) {
    int e = blockIdx.x * 256 + threadIdx.x;
    if (e >= NOFF * 64 * 40) return;
    int c = e % 40;
    int rest = e / 40;
    int ci = rest % 64;
    int k = rest / 64;
    float v = (c < 38) ? W1[(k * 64 + ci) * 38 + c] : 0.0f;
    g_W1p[e] = tf32r(v);
}

__global__ void prep_w2(const float* __restrict__ W2) {
    int e = blockIdx.x * 256 + threadIdx.x;
    if (e >= NOFF * 40 * 40) return;
    int c = e % 40;
    int rest = e / 40;
    int ci = rest % 40;
    int k = rest / 40;
    float v = (c < 38 && ci < 38) ? W2[(k * 38 + ci) * 38 + c] : 0.0f;
    g_W2p[e] = tf32r(v);
}

// ------------------------------ conv kernel -------------------------------
// 128 threads = 4 warps; thread t owns A-row t. CTA tile: 128 rows x 40 cols.
// Warp w owns rows 32w..32w+31 = its own 32 lanes -> ballot gives tile validity.
// MODE 0: in = g_featp (KD=64), out = g_h with exact-GELU + tf32 rounding
// MODE 1: in = g_h    (KD=40), out = d_out (first 38 cols)

template <int KD, int MODE>
__global__ __launch_bounds__(128) void conv_k(const int* __restrict__ nbr,
                                              float* __restrict__ dout) {
    constexpr int KD4 = KD / 4;
    constexpr int AS  = KD + 4;          // padded smem stride (bank-conflict-free)
    __shared__ float As[128 * AS];
    __shared__ float Ws[2][KD * 40];     // double-buffered weights

    const float* __restrict__ feat = (MODE == 0) ? g_featp : g_h;
    const float* __restrict__ Wg   = (MODE == 0) ? g_W1p   : g_W2p;

    const int tid  = threadIdx.x;
    const int warp = tid >> 5;
    const int lane = tid & 31;
    const int g    = lane >> 2;   // group id (0..7)
    const int t    = lane & 3;    // thread in group (0..3)
    const int base = blockIdx.x * 128;

    const unsigned as_base = (unsigned)__cvta_generic_to_shared(As);
    const unsigned ws_base = (unsigned)__cvta_generic_to_shared(Ws);

    float acc[2][5][4];
#pragma unroll
    for (int tt = 0; tt < 2; tt++)
#pragma unroll
        for (int j = 0; j < 5; j++)
#pragma unroll
            for (int q = 0; q < 4; q++) acc[tt][j][q] = 0.0f;

    const float4* __restrict__ feat4 = (const float4*)feat;

    // preload W[0] into buffer 0
    {
        const float4* wsrc = (const float4*)Wg;
#pragma unroll
        for (int e = tid; e < KD * 10; e += 128)
            asm volatile("cp.async.ca.shared.global [%0], [%1], 16;"
                         :: "r"(ws_base + (unsigned)(16 * e)), "l"(wsrc + e));
        asm volatile("cp.async.commit_group;" ::: "memory");
    }

    // zero own A row once; afterwards rewrite only on state change
    {
        const float4 z = make_float4(0.f, 0.f, 0.f, 0.f);
#pragma unroll
        for (int m = 0; m < KD4; m++)
            *(float4*)&As[tid * AS + 4 * m] = z;
    }
    bool dirty = false;

    for (int k = 0; k < NOFF; k++) {
        // (end-of-previous-iteration __syncthreads guarantees MMA k-1 is done
        //  reading As before we overwrite it)

        // --- gather A row (skip invalid; re-zero only on valid->invalid) ---
        const int idx = __ldg(&nbr[k * NPTS + base + tid]);
        const bool valid = (unsigned)idx < (unsigned)NPTS;
        const unsigned ball = __ballot_sync(0xFFFFFFFFu, valid);
        if (valid) {
            const float4* src = feat4 + (size_t)idx * KD4;
            const unsigned dst = as_base + (unsigned)(tid * AS) * 4u;
#pragma unroll
            for (int m = 0; m < KD4; m++)
                asm volatile("cp.async.ca.shared.global [%0], [%1], 16;"
                             :: "r"(dst + (unsigned)(16 * m)), "l"(src + m));
        } else if (dirty) {
            const float4 z = make_float4(0.f, 0.f, 0.f, 0.f);
#pragma unroll
            for (int m = 0; m < KD4; m++)
                *(float4*)&As[tid * AS + 4 * m] = z;
        }
        dirty = valid;
        asm volatile("cp.async.commit_group;" ::: "memory");   // group: A(k)

        // --- prefetch W[k+1] into the other buffer (separate group) ---
        if (k + 1 < NOFF) {
            const float4* wsrc = (const float4*)(Wg + (k + 1) * KD * 40);
            const unsigned wb = ws_base + (unsigned)(((k + 1) & 1) * KD * 40 * 4);
#pragma unroll
            for (int e = tid; e < KD * 10; e += 128)
                asm volatile("cp.async.ca.shared.global [%0], [%1], 16;"
                             :: "r"(wb + (unsigned)(16 * e)), "l"(wsrc + e));
            asm volatile("cp.async.commit_group;" ::: "memory"); // group: W(k+1)
            asm volatile("cp.async.wait_group 1;" ::: "memory"); // A(k)+W(k) done
        } else {
            asm volatile("cp.async.wait_group 0;" ::: "memory");
        }
        __syncthreads();

        // --- MMA: [128 x KD] @ [KD x 40]; skip all-invalid 16-row tiles ---
        const bool s0 = (ball & 0xFFFFu) == 0u;     // rows 32w..32w+15 all invalid
        const bool s1 = (ball >> 16) == 0u;         // rows 32w+16..32w+31 all invalid
        if (!(s0 && s1)) {
            const float* __restrict__ W = Ws[k & 1];
#pragma unroll
            for (int kk = 0; kk < KD / 8; ++kk) {
                const int kc = kk * 8 + t;
                unsigned a[2][4];
                if (!s0) {
                    const int arow = warp * 32 + g;
                    a[0][0] = __float_as_uint(As[arow * AS + kc]);
                    a[0][1] = __float_as_uint(As[(arow + 8) * AS + kc]);
                    a[0][2] = __float_as_uint(As[arow * AS + kc + 4]);
                    a[0][3] = __float_as_uint(As[(arow + 8) * AS + kc + 4]);
                }
                if (!s1) {
                    const int arow = warp * 32 + 16 + g;
                    a[1][0] = __float_as_uint(As[arow * AS + kc]);
                    a[1][1] = __float_as_uint(As[(arow + 8) * AS + kc]);
                    a[1][2] = __float_as_uint(As[arow * AS + kc + 4]);
                    a[1][3] = __float_as_uint(As[(arow + 8) * AS + kc + 4]);
                }
#pragma unroll
                for (int j = 0; j < 5; j++) {
                    const unsigned b0 = __float_as_uint(W[kc * 40 + j * 8 + g]);
                    const unsigned b1 = __float_as_uint(W[(kc + 4) * 40 + j * 8 + g]);
                    if (!s0)
                        asm volatile(
                            "mma.sync.aligned.m16n8k8.row.col.f32.tf32.tf32.f32 "
                            "{%0,%1,%2,%3}, {%4,%5,%6,%7}, {%8,%9}, {%0,%1,%2,%3};\n"
                            : "+f"(acc[0][j][0]), "+f"(acc[0][j][1]),
                              "+f"(acc[0][j][2]), "+f"(acc[0][j][3])
                            : "r"(a[0][0]), "r"(a[0][1]), "r"(a[0][2]),
                              "r"(a[0][3]), "r"(b0), "r"(b1));
                    if (!s1)
                        asm volatile(
                            "mma.sync.aligned.m16n8k8.row.col.f32.tf32.tf32.f32 "
                            "{%0,%1,%2,%3}, {%4,%5,%6,%7}, {%8,%9}, {%0,%1,%2,%3};\n"
                            : "+f"(acc[1][j][0]), "+f"(acc[1][j][1]),
                              "+f"(acc[1][j][2]), "+f"(acc[1][j][3])
                            : "r"(a[1][0]), "r"(a[1][1]), "r"(a[1][2]),
                              "r"(a[1][3]), "r"(b0), "r"(b1));
                }
            }
        }
        __syncthreads();
    }

    // --- epilogue ---
#pragma unroll
    for (int tt = 0; tt < 2; tt++) {
        const int r0 = base + warp * 32 + tt * 16 + g;
#pragma unroll
        for (int j = 0; j < 5; j++) {
            const int c0 = j * 8 + 2 * t;
            if (MODE == 0) {
                g_h[r0 * 40 + c0]           = tf32r(gelu_exact(acc[tt][j][0]));
                g_h[r0 * 40 + c0 + 1]       = tf32r(gelu_exact(acc[tt][j][1]));
                g_h[(r0 + 8) * 40 + c0]     = tf32r(gelu_exact(acc[tt][j][2]));
                g_h[(r0 + 8) * 40 + c0 + 1] = tf32r(gelu_exact(acc[tt][j][3]));
            } else {
                if (c0 < 38) {
                    dout[r0 * 38 + c0]       = acc[tt][j][0];
                    dout[(r0 + 8) * 38 + c0] = acc[tt][j][2];
                }
                if (c0 + 1 < 38) {
                    dout[r0 * 38 + c0 + 1]       = acc[tt][j][1];
                    dout[(r0 + 8) * 38 + c0 + 1] = acc[tt][j][3];
                }
            }
        }
    }
}

// ------------------------------ launch ------------------------------------

extern "C" void kernel_launch(void* const* d_in, const int* in_sizes, int n_in,
                              void* d_out, int out_size) {
    const float* F   = (const float*)d_in[0];   // [400000, 64]
    const int*   nbr = (const int*)d_in[1];     // [27, 400000]
    const float* W1  = (const float*)d_in[2];   // [27, 64, 38]
    const float* W2  = (const float*)d_in[3];   // [27, 38, 38]
    float* out = (float*)d_out;                 // [400000, 38]

    prep_feat<<<(NPTS * 64) / 256, 256>>>(F);               // exact multiple
    prep_w1<<<(NOFF * 64 * 40 + 255) / 256, 256>>>(W1);
    prep_w2<<<(NOFF * 40 * 40 + 255) / 256, 256>>>(W2);

    conv_k<64, 0><<<NPTS / 128, 128>>>(nbr, nullptr);       // L1 + GELU -> g_h
    conv_k<40, 1><<<NPTS / 128, 128>>>(nbr, out);           // L2 -> d_out
}

// round 6
// speedup vs baseline: 1.6316x; 1.6316x over previous
#include <cuda_runtime.h>
#include <cuda_fp16.h>
#include <cstdint>

// ---------------------------------------------------------------------------
// SparseGaussianHead: two sparse-conv layers (27-offset gather-GEMM) + GELU
//   L1: [400k x 64] -> [400k x 38]   (N padded to 40)
//   L2: [400k x 38] -> [400k x 38]   (K padded to 48, N padded to 40)
// R5: fp16 m16n8k16 MMA (same 10-bit mantissa as tf32, half the LDS/gather
//     bytes, half the MMA count), fp32 accumulate. R2 loop structure.
// ---------------------------------------------------------------------------

#define NPTS 400000
#define NOFF 27

// fp16 feature/intermediate storage + pre-transposed fp16 weight images
__device__ __half g_feat[NPTS * 64];          // features, fp16
__device__ __half g_h[NPTS * 48];             // gelu out, cols 38..47 = 0
__device__ __half g_W1t[NOFF * 40 * 72];      // W1^T [k][n][c], stride 72 halves
__device__ __half g_W2t[NOFF * 40 * 56];      // W2^T [k][n][c], stride 56 halves

__device__ __forceinline__ float gelu_exact(float x) {
    return 0.5f * x * (1.0f + erff(x * 0.7071067811865476f));
}

// ------------------------------ prep kernels ------------------------------

__global__ void prep_feat(const float* __restrict__ F) {
    int e = blockIdx.x * 256 + threadIdx.x;   // NPTS*64 exact multiple of 256
    g_feat[e] = __float2half_rn(F[e]);
}

__global__ void prep_w1(const float* __restrict__ W1) {
    int e = blockIdx.x * 256 + threadIdx.x;
    if (e >= NOFF * 40 * 64) return;
    int c = e & 63;               // input channel (K dim), 0..63
    int n = (e >> 6) % 40;        // output channel, 0..39
    int k = e / (64 * 40);
    float v = (n < 38) ? W1[(k * 64 + c) * 38 + n] : 0.0f;
    g_W1t[k * (40 * 72) + n * 72 + c] = __float2half_rn(v);
}

__global__ void prep_w2(const float* __restrict__ W2) {
    int e = blockIdx.x * 256 + threadIdx.x;
    if (e >= NOFF * 40 * 48) return;
    int c = e % 48;               // input channel (K dim), 0..47
    int rest = e / 48;
    int n = rest % 40;
    int k = rest / 40;
    float v = (n < 38 && c < 38) ? W2[(k * 38 + c) * 38 + n] : 0.0f;
    g_W2t[k * (40 * 56) + n * 56 + c] = __float2half_rn(v);
}

// ------------------------------ conv kernel -------------------------------
// 128 threads = 4 warps; warp w owns rows 32w..32w+31 (two m16 tiles).
// KD = 64 (conv1) or 48 (conv2). AS = padded half-stride (72 / 56):
// bank index for fragment loads = (4g + t + const) mod 32 -> conflict-free.
// MODE 0: in g_feat, out g_h (exact GELU, fp16 round, cols 40..47 zeroed)
// MODE 1: in g_h,    out d_out (first 38 cols, fp32)

template <int KD, int MODE>
__global__ __launch_bounds__(128) void conv_k(const int* __restrict__ nbr,
                                              float* __restrict__ dout) {
    constexpr int AS   = (KD == 64) ? 72 : 56;  // halves per A/W row (16B mult)
    constexpr int CHK  = KD / 8;                // 16B chunks per A row (8 / 6)
    constexpr int KK   = KD / 16;               // K-steps (4 / 3)
    constexpr int WCHK = 5 * AS;                // 16B chunks in W tile (40*AS*2/16)

    __shared__ __half As[128 * AS];
    __shared__ __half Ws[40 * AS];

    const __half* __restrict__ feat = (MODE == 0) ? g_feat : g_h;
    const __half* __restrict__ Wg   = (MODE == 0) ? g_W1t  : g_W2t;

    const int tid  = threadIdx.x;
    const int warp = tid >> 5;
    const int lane = tid & 31;
    const int g    = lane >> 2;   // 0..7
    const int t    = lane & 3;    // 0..3
    const int base = blockIdx.x * 128;

    const unsigned as_base = (unsigned)__cvta_generic_to_shared(As);
    const unsigned ws_base = (unsigned)__cvta_generic_to_shared(Ws);

    float acc[2][5][4];
#pragma unroll
    for (int tt = 0; tt < 2; tt++)
#pragma unroll
        for (int j = 0; j < 5; j++)
#pragma unroll
            for (int q = 0; q < 4; q++) acc[tt][j][q] = 0.0f;

    for (int k = 0; k < NOFF; k++) {
        __syncthreads();   // previous iteration's MMAs done reading smem

        // --- gather A tile: thread tid owns row tid (zfill when invalid) ---
        {
            const int idx = __ldg(&nbr[k * NPTS + base + tid]);
            const unsigned vsz = ((unsigned)idx < (unsigned)NPTS) ? 16u : 0u;
            const char* src = (const char*)(feat + (size_t)(vsz ? idx : 0) * KD);
            const unsigned dst = as_base + (unsigned)(tid * AS) * 2u;
#pragma unroll
            for (int m = 0; m < CHK; m++)
                asm volatile("cp.async.ca.shared.global [%0], [%1], 16, %2;"
                             :: "r"(dst + (unsigned)(16 * m)),
                                "l"(src + 16 * m), "r"(vsz));
        }
        // --- W tile: flat copy of pre-transposed image (40 x AS halves) ---
        {
            const char* wsrc = (const char*)(Wg + (size_t)k * 40 * AS);
#pragma unroll
            for (int e = tid; e < WCHK; e += 128)
                asm volatile("cp.async.ca.shared.global [%0], [%1], 16;"
                             :: "r"(ws_base + (unsigned)(16 * e)),
                                "l"(wsrc + 16 * e));
        }
        asm volatile("cp.async.commit_group;" ::: "memory");
        asm volatile("cp.async.wait_group 0;" ::: "memory");
        __syncthreads();

        // --- MMA: [128 x KD] @ [KD x 40] in m16n8k16 steps ---
#pragma unroll
        for (int kk = 0; kk < KK; ++kk) {
            const int kc = kk * 16 + 2 * t;
            unsigned a[2][4];
#pragma unroll
            for (int tt = 0; tt < 2; tt++) {
                const int r = warp * 32 + tt * 16 + g;
                a[tt][0] = *(const unsigned*)&As[r * AS + kc];
                a[tt][1] = *(const unsigned*)&As[(r + 8) * AS + kc];
                a[tt][2] = *(const unsigned*)&As[r * AS + kc + 8];
                a[tt][3] = *(const unsigned*)&As[(r + 8) * AS + kc + 8];
            }
#pragma unroll
            for (int j = 0; j < 5; j++) {
                const unsigned b0 = *(const unsigned*)&Ws[(j * 8 + g) * AS + kc];
                const unsigned b1 = *(const unsigned*)&Ws[(j * 8 + g) * AS + kc + 8];
#pragma unroll
                for (int tt = 0; tt < 2; tt++) {
                    asm volatile(
                        "mma.sync.aligned.m16n8k16.row.col.f32.f16.f16.f32 "
                        "{%0,%1,%2,%3}, {%4,%5,%6,%7}, {%8,%9}, {%0,%1,%2,%3};\n"
                        : "+f"(acc[tt][j][0]), "+f"(acc[tt][j][1]),
                          "+f"(acc[tt][j][2]), "+f"(acc[tt][j][3])
                        : "r"(a[tt][0]), "r"(a[tt][1]), "r"(a[tt][2]),
                          "r"(a[tt][3]), "r"(b0), "r"(b1));
                }
            }
        }
    }

    // --- epilogue ---
#pragma unroll
    for (int tt = 0; tt < 2; tt++) {
        const int r0 = base + warp * 32 + tt * 16 + g;
#pragma unroll
        for (int j = 0; j < 5; j++) {
            const int c0 = j * 8 + 2 * t;
            if (MODE == 0) {
                __half2* h0 = (__half2*)&g_h[(size_t)r0 * 48 + c0];
                __half2* h1 = (__half2*)&g_h[(size_t)(r0 + 8) * 48 + c0];
                *h0 = __floats2half2_rn(gelu_exact(acc[tt][j][0]),
                                        gelu_exact(acc[tt][j][1]));
                *h1 = __floats2half2_rn(gelu_exact(acc[tt][j][2]),
                                        gelu_exact(acc[tt][j][3]));
            } else {
                if (c0 < 38) {
                    dout[(size_t)r0 * 38 + c0]       = acc[tt][j][0];
                    dout[(size_t)(r0 + 8) * 38 + c0] = acc[tt][j][2];
                }
                if (c0 + 1 < 38) {
                    dout[(size_t)r0 * 38 + c0 + 1]       = acc[tt][j][1];
                    dout[(size_t)(r0 + 8) * 38 + c0 + 1] = acc[tt][j][3];
                }
            }
        }
        // zero pad cols 40..47 of g_h (t==0 lane covers its two rows)
        if (MODE == 0 && t == 0) {
            *(float4*)&g_h[(size_t)r0 * 48 + 40]       = make_float4(0.f, 0.f, 0.f, 0.f);
            *(float4*)&g_h[(size_t)(r0 + 8) * 48 + 40] = make_float4(0.f, 0.f, 0.f, 0.f);
        }
    }
}

// ------------------------------ launch ------------------------------------

extern "C" void kernel_launch(void* const* d_in, const int* in_sizes, int n_in,
                              void* d_out, int out_size) {
    const float* F   = (const float*)d_in[0];   // [400000, 64]
    const int*   nbr = (const int*)d_in[1];     // [27, 400000]
    const float* W1  = (const float*)d_in[2];   // [27, 64, 38]
    const float* W2  = (const float*)d_in[3];   // [27, 38, 38]
    float* out = (float*)d_out;                 // [400000, 38]

    prep_feat<<<(NPTS * 64) / 256, 256>>>(F);
    prep_w1<<<(NOFF * 40 * 64 + 255) / 256, 256>>>(W1);
    prep_w2<<<(NOFF * 40 * 48 + 255) / 256, 256>>>(W2);

    conv_k<64, 0><<<NPTS / 128, 128>>>(nbr, nullptr);   // L1 + GELU -> g_h
    conv_k<48, 1><<<NPTS / 128, 128>>>(nbr, out);       // L2 -> d_out
}